// round 1
// baseline (speedup 1.0000x reference)
#include <cuda_runtime.h>
#include <cstdint>
#include <cstddef>

// Problem constants
#define T_TOK 8192
#define DHID  1024
#define NE    8
#define TK    4

// GEMM tiling
#define BM 128
#define BN 128
#define BK 8
#define MTILES 264                 // capacity: 32768 rows + per-expert padding to 128
#define ROWS_CAP (MTILES * BM)     // 33792

// ---------------- scratch (device globals; no allocation) ----------------
__device__ float g_Y[(size_t)ROWS_CAP * DHID];   // per-(token,expert) GEMM results
__device__ int   g_pair_tok[ROWS_CAP];           // token id per GEMM row (-1 = pad)
__device__ int   g_slot[T_TOK * TK];             // (t,k) -> GEMM row
__device__ int   g_topk_e[T_TOK * TK];
__device__ float g_topk_w[T_TOK * TK];
__device__ float g_probs[T_TOK * NE];
__device__ int   g_counts[NE];
__device__ int   g_cursor[NE];
__device__ int   g_off[NE + 1];                  // 128-aligned group offsets

// ---------------- kernel 0: zero counters ----------------
__global__ void init_kernel() {
    int i = threadIdx.x;
    if (i < NE) { g_counts[i] = 0; g_cursor[i] = 0; }
}

// ---------------- kernel 1: router ----------------
// one block (128 threads) per token: logits = x[t]@Wg + bg, softmax, top-4
__global__ __launch_bounds__(128) void router_kernel(
    const float* __restrict__ x, const float* __restrict__ Wg,
    const float* __restrict__ bg)
{
    int t = blockIdx.x;
    const float* xr = x + (size_t)t * DHID;
    float acc[NE];
#pragma unroll
    for (int e = 0; e < NE; e++) acc[e] = 0.f;

    for (int d = threadIdx.x; d < DHID; d += 128) {
        float xv = xr[d];
        const float* wr = Wg + d * NE;
#pragma unroll
        for (int e = 0; e < NE; e++) acc[e] = fmaf(xv, wr[e], acc[e]);
    }
    // warp reduce (fixed order -> deterministic)
#pragma unroll
    for (int off = 16; off > 0; off >>= 1)
#pragma unroll
        for (int e = 0; e < NE; e++)
            acc[e] += __shfl_down_sync(0xffffffffu, acc[e], off);

    __shared__ float s[4][NE];
    int warp = threadIdx.x >> 5, lane = threadIdx.x & 31;
    if (lane == 0)
#pragma unroll
        for (int e = 0; e < NE; e++) s[warp][e] = acc[e];
    __syncthreads();

    if (threadIdx.x == 0) {
        float logit[NE], p[NE];
        float mx = -1e30f;
#pragma unroll
        for (int e = 0; e < NE; e++) {
            logit[e] = s[0][e] + s[1][e] + s[2][e] + s[3][e] + bg[e];
            mx = fmaxf(mx, logit[e]);
        }
        float sum = 0.f;
#pragma unroll
        for (int e = 0; e < NE; e++) { p[e] = __expf(logit[e] - mx); sum += p[e]; }
        float inv = 1.0f / sum;
#pragma unroll
        for (int e = 0; e < NE; e++) { p[e] *= inv; g_probs[t * NE + e] = p[e]; }

        // top-4 (ties -> lowest index, matches lax.top_k)
        bool used[NE];
#pragma unroll
        for (int e = 0; e < NE; e++) used[e] = false;
        int   idxs[TK];
        float vals[TK];
        float psel = 0.f;
#pragma unroll
        for (int k = 0; k < TK; k++) {
            int best = -1; float bv = -1.f;
#pragma unroll
            for (int e = 0; e < NE; e++)
                if (!used[e] && p[e] > bv) { bv = p[e]; best = e; }
            used[best] = true;
            idxs[k] = best; vals[k] = bv; psel += bv;
        }
        float winv = 1.0f / (psel + 1e-6f);
#pragma unroll
        for (int k = 0; k < TK; k++) {
            g_topk_e[t * TK + k] = idxs[k];
            g_topk_w[t * TK + k] = vals[k] * winv;
            atomicAdd(&g_counts[idxs[k]], 1);
        }
    }
}

// ---------------- kernel 2: deterministic probs reduce + scan + aux ----------------
__global__ __launch_bounds__(256) void finalize_kernel(float* aux_out)
{
    __shared__ float sh[256];
    int tid = threadIdx.x;
    int e = tid & 7, g = tid >> 3;   // 32 groups x 8 experts
    float sum = 0.f;
    for (int t = g; t < T_TOK; t += 32) sum += g_probs[t * NE + e];
    sh[tid] = sum;
    __syncthreads();
#pragma unroll
    for (int st = 128; st >= 8; st >>= 1) {
        if (tid < st) sh[tid] += sh[tid + st];
        __syncthreads();
    }
    if (tid == 0) {
        // offsets padded to BM so every GEMM m-tile is single-expert
        int o = 0;
        g_off[0] = 0;
#pragma unroll
        for (int i = 0; i < NE; i++) {
            o += ((g_counts[i] + BM - 1) / BM) * BM;
            g_off[i + 1] = o;
        }
        // aux = 8/T^2 * sum_e counts[e] * probs_sum[e]
        float aux = 0.f;
#pragma unroll
        for (int i = 0; i < NE; i++) aux += (float)g_counts[i] * sh[i];
        aux *= (float)NE / ((float)T_TOK * (float)T_TOK);
        if (aux_out) *aux_out = aux;
    }
}

// ---------------- kernel 3: fill pad markers ----------------
__global__ void fill_kernel() {
    int i = blockIdx.x * blockDim.x + threadIdx.x;
    if (i < ROWS_CAP) g_pair_tok[i] = -1;
}

// ---------------- kernel 4: build pair list ----------------
__global__ void build_kernel() {
    int t = blockIdx.x * blockDim.x + threadIdx.x;
    if (t >= T_TOK) return;
#pragma unroll
    for (int k = 0; k < TK; k++) {
        int e = g_topk_e[t * TK + k];
        int pos = g_off[e] + atomicAdd(&g_cursor[e], 1);
        g_pair_tok[pos] = t;
        g_slot[t * TK + k] = pos;
    }
}

// ---------------- kernel 5: grouped SGEMM (gathered A) ----------------
// Y[row, :] = x[pair_tok[row], :] @ W[expert(row)]
__global__ __launch_bounds__(256) void gemm_kernel(
    const float* __restrict__ x, const float* __restrict__ W)
{
    __shared__ float As[BK][BM];
    __shared__ float Bs[BK][BN];

    const int n0 = blockIdx.x * BN;
    const int m0 = blockIdx.y * BM;
    const int tid = threadIdx.x;

    // expert for this m-tile (tiles never straddle experts thanks to padding)
    int e = 0;
#pragma unroll
    for (int i = 1; i < NE; i++) if (m0 >= g_off[i]) e = i;
    const float* __restrict__ Wb = W + (size_t)e * DHID * DHID;

    // A loader: thread -> (row, 4 k's)
    const int rloc = tid >> 1;
    const int akp  = (tid & 1) * 4;
    const int tok  = g_pair_tok[m0 + rloc];
    const float* __restrict__ xrow = x + (size_t)(tok < 0 ? 0 : tok) * DHID;

    // B loader: thread -> (k-row, 4 n's)
    const int brow = tid >> 5;
    const int bcol = (tid & 31) << 2;

    const int tx = tid & 15, ty = tid >> 4;

    float acc[8][8];
#pragma unroll
    for (int i = 0; i < 8; i++)
#pragma unroll
        for (int j = 0; j < 8; j++) acc[i][j] = 0.f;

    const float4 z4 = make_float4(0.f, 0.f, 0.f, 0.f);
    float4 aReg = (tok >= 0) ? *(const float4*)(xrow + akp) : z4;
    float4 bReg = *(const float4*)(Wb + (size_t)brow * DHID + n0 + bcol);

    for (int k0 = 0; k0 < DHID; k0 += BK) {
        As[akp + 0][rloc] = aReg.x;
        As[akp + 1][rloc] = aReg.y;
        As[akp + 2][rloc] = aReg.z;
        As[akp + 3][rloc] = aReg.w;
        *(float4*)&Bs[brow][bcol] = bReg;
        __syncthreads();

        if (k0 + BK < DHID) {   // prefetch next tile into registers
            aReg = (tok >= 0) ? *(const float4*)(xrow + k0 + BK + akp) : z4;
            bReg = *(const float4*)(Wb + (size_t)(k0 + BK + brow) * DHID + n0 + bcol);
        }

#pragma unroll
        for (int kk = 0; kk < BK; kk++) {
            float4 a0 = *(const float4*)&As[kk][ty * 8];
            float4 a1 = *(const float4*)&As[kk][ty * 8 + 4];
            float4 b0 = *(const float4*)&Bs[kk][tx * 8];
            float4 b1 = *(const float4*)&Bs[kk][tx * 8 + 4];
            float ar[8] = {a0.x, a0.y, a0.z, a0.w, a1.x, a1.y, a1.z, a1.w};
            float br[8] = {b0.x, b0.y, b0.z, b0.w, b1.x, b1.y, b1.z, b1.w};
#pragma unroll
            for (int i = 0; i < 8; i++)
#pragma unroll
                for (int j = 0; j < 8; j++)
                    acc[i][j] = fmaf(ar[i], br[j], acc[i][j]);
        }
        __syncthreads();
    }

#pragma unroll
    for (int i = 0; i < 8; i++) {
        int row = m0 + ty * 8 + i;
        float* yr = g_Y + (size_t)row * DHID + n0 + tx * 8;
        *(float4*)yr       = make_float4(acc[i][0], acc[i][1], acc[i][2], acc[i][3]);
        *(float4*)(yr + 4) = make_float4(acc[i][4], acc[i][5], acc[i][6], acc[i][7]);
    }
}

// ---------------- kernel 6: weighted combine (fixed k order -> deterministic) ----------------
__global__ __launch_bounds__(256) void combine_kernel(
    const float* __restrict__ b, float* __restrict__ out)
{
    int idx = blockIdx.x * blockDim.x + threadIdx.x;   // over T*D/4
    int t = idx >> 8;
    int f = (idx & 255) << 2;
    float4 r = make_float4(0.f, 0.f, 0.f, 0.f);
#pragma unroll
    for (int k = 0; k < TK; k++) {
        int e  = g_topk_e[t * TK + k];
        float w = g_topk_w[t * TK + k];
        int sl = g_slot[t * TK + k];
        float4 yv = *(const float4*)(g_Y + (size_t)sl * DHID + f);
        float4 bv = *(const float4*)(b + (size_t)e * DHID + f);
        r.x = fmaf(w, yv.x + bv.x, r.x);
        r.y = fmaf(w, yv.y + bv.y, r.y);
        r.z = fmaf(w, yv.z + bv.z, r.z);
        r.w = fmaf(w, yv.w + bv.w, r.w);
    }
    *(float4*)(out + (size_t)t * DHID + f) = r;
}

// ---------------- launch ----------------
extern "C" void kernel_launch(void* const* d_in, const int* in_sizes, int n_in,
                              void* d_out, int out_size)
{
    const float* x  = (const float*)d_in[0];
    const float* Wg = (const float*)d_in[1];
    const float* bg = (const float*)d_in[2];
    const float* W  = (const float*)d_in[3];
    const float* b  = (const float*)d_in[4];
    float* out = (float*)d_out;

    float* aux_out = (out_size > T_TOK * DHID) ? out + (size_t)T_TOK * DHID : nullptr;

    init_kernel<<<1, 32>>>();
    router_kernel<<<T_TOK, 128>>>(x, Wg, bg);
    finalize_kernel<<<1, 256>>>(aux_out);
    fill_kernel<<<(ROWS_CAP + 255) / 256, 256>>>();
    build_kernel<<<(T_TOK + 255) / 256, 256>>>();
    gemm_kernel<<<dim3(DHID / BN, MTILES), 256>>>(x, W);
    combine_kernel<<<(T_TOK * DHID / 4 + 255) / 256, 256>>>(b, out);
}

// round 3
// speedup vs baseline: 1.6144x; 1.6144x over previous
#include <cuda_runtime.h>
#include <cuda_bf16.h>
#include <cstdint>
#include <cstddef>

// Problem constants
#define T_TOK 8192
#define DHID  1024
#define NE    8
#define TK    4

// GEMM config
#define BM    128
#define BN    128
#define BKB   64                  // k per stage chunk (per half)
#define NST   3
#define KHALF 1024
#define NK    (KHALF / BKB)       // 16
#define MTILES 264
#define ROWS_CAP (MTILES * BM)    // 33792

// smem stage layout (bytes): padded rows for conflict-free ldmatrix
// A rows: 64 elems -> 72 (144B); B rows: 128 elems -> 136 (272B)
#define AH_OFF 0
#define AL_OFF 18432
#define BH_OFF 36864
#define BL_OFF 54272
#define STAGE_BYTES 71680
#define SMEM_DYN (NST * STAGE_BYTES)   // 215040

// ---------------- scratch (device globals; no allocation) ----------------
__device__ __nv_bfloat16 g_A2[(size_t)T_TOK * 2048];          // per token: [hi(1024) | lo(1024)]
__device__ __nv_bfloat16 g_B2[(size_t)NE * 2048 * DHID];      // per expert: [Wh(1024)|Wl(1024)][n]
__device__ float g_Y[(size_t)ROWS_CAP * DHID];
__device__ int   g_pair_tok[ROWS_CAP];
__device__ int   g_slot[T_TOK * TK];
__device__ int   g_topk_e[T_TOK * TK];
__device__ float g_topk_w[T_TOK * TK];
__device__ float g_probs[T_TOK * NE];
__device__ int   g_counts[NE];
__device__ int   g_cursor[NE];
__device__ int   g_off[NE + 1];

// ---------------- PTX helpers (all sm_80-compatible) ----------------
__device__ __forceinline__ uint32_t smem_u32(const void* p) {
    uint32_t a;
    asm("{ .reg .u64 t; cvta.to.shared.u64 t, %1; cvt.u32.u64 %0, t; }" : "=r"(a) : "l"(p));
    return a;
}
__device__ __forceinline__ void cp16(uint32_t dst, const void* src) {
    asm volatile("cp.async.cg.shared.global [%0], [%1], 16;" :: "r"(dst), "l"(src));
}
__device__ __forceinline__ void cp16z(uint32_t dst, const void* src, int sz) {
    asm volatile("cp.async.cg.shared.global [%0], [%1], 16, %2;" :: "r"(dst), "l"(src), "r"(sz));
}
#define CP_COMMIT() asm volatile("cp.async.commit_group;" ::: "memory")
#define CP_WAIT(n)  asm volatile("cp.async.wait_group %0;" :: "n"(n) : "memory")

__device__ __forceinline__ void ldsm4(uint32_t* r, uint32_t addr) {
    asm volatile("ldmatrix.sync.aligned.m8n8.x4.shared.b16 {%0,%1,%2,%3}, [%4];"
        : "=r"(r[0]), "=r"(r[1]), "=r"(r[2]), "=r"(r[3]) : "r"(addr));
}
__device__ __forceinline__ void ldsm4t(uint32_t* r, uint32_t addr) {
    asm volatile("ldmatrix.sync.aligned.m8n8.x4.trans.shared.b16 {%0,%1,%2,%3}, [%4];"
        : "=r"(r[0]), "=r"(r[1]), "=r"(r[2]), "=r"(r[3]) : "r"(addr));
}
__device__ __forceinline__ void mma16816(float* c, const uint32_t* a, const uint32_t* b) {
    asm volatile("mma.sync.aligned.m16n8k16.row.col.f32.bf16.bf16.f32 "
        "{%0,%1,%2,%3}, {%4,%5,%6,%7}, {%8,%9}, {%0,%1,%2,%3};"
        : "+f"(c[0]), "+f"(c[1]), "+f"(c[2]), "+f"(c[3])
        : "r"(a[0]), "r"(a[1]), "r"(a[2]), "r"(a[3]), "r"(b[0]), "r"(b[1]));
}

// ---------------- kernel 0: zero counters ----------------
__global__ void init_kernel() {
    int i = threadIdx.x;
    if (i < NE) { g_counts[i] = 0; g_cursor[i] = 0; }
}

// ---------------- kernel 1: router ----------------
__global__ __launch_bounds__(128) void router_kernel(
    const float* __restrict__ x, const float* __restrict__ Wg,
    const float* __restrict__ bg)
{
    int t = blockIdx.x;
    const float* xr = x + (size_t)t * DHID;
    float acc[NE];
#pragma unroll
    for (int e = 0; e < NE; e++) acc[e] = 0.f;

    for (int d = threadIdx.x; d < DHID; d += 128) {
        float xv = xr[d];
        const float* wr = Wg + d * NE;
#pragma unroll
        for (int e = 0; e < NE; e++) acc[e] = fmaf(xv, wr[e], acc[e]);
    }
#pragma unroll
    for (int off = 16; off > 0; off >>= 1)
#pragma unroll
        for (int e = 0; e < NE; e++)
            acc[e] += __shfl_down_sync(0xffffffffu, acc[e], off);

    __shared__ float s[4][NE];
    int warp = threadIdx.x >> 5, lane = threadIdx.x & 31;
    if (lane == 0)
#pragma unroll
        for (int e = 0; e < NE; e++) s[warp][e] = acc[e];
    __syncthreads();

    if (threadIdx.x == 0) {
        float logit[NE], p[NE];
        float mx = -1e30f;
#pragma unroll
        for (int e = 0; e < NE; e++) {
            logit[e] = s[0][e] + s[1][e] + s[2][e] + s[3][e] + bg[e];
            mx = fmaxf(mx, logit[e]);
        }
        float sum = 0.f;
#pragma unroll
        for (int e = 0; e < NE; e++) { p[e] = __expf(logit[e] - mx); sum += p[e]; }
        float inv = 1.0f / sum;
#pragma unroll
        for (int e = 0; e < NE; e++) { p[e] *= inv; g_probs[t * NE + e] = p[e]; }

        bool used[NE];
#pragma unroll
        for (int e = 0; e < NE; e++) used[e] = false;
        int   idxs[TK];
        float vals[TK];
        float psel = 0.f;
#pragma unroll
        for (int k = 0; k < TK; k++) {
            int best = -1; float bv = -1.f;
#pragma unroll
            for (int e = 0; e < NE; e++)
                if (!used[e] && p[e] > bv) { bv = p[e]; best = e; }
            used[best] = true;
            idxs[k] = best; vals[k] = bv; psel += bv;
        }
        float winv = 1.0f / (psel + 1e-6f);
#pragma unroll
        for (int k = 0; k < TK; k++) {
            g_topk_e[t * TK + k] = idxs[k];
            g_topk_w[t * TK + k] = vals[k] * winv;
            atomicAdd(&g_counts[idxs[k]], 1);
        }
    }
}

// ---------------- kernel 2: deterministic probs reduce + scan + aux ----------------
__global__ __launch_bounds__(256) void finalize_kernel(float* aux_out)
{
    __shared__ float sh[256];
    int tid = threadIdx.x;
    int e = tid & 7, g = tid >> 3;
    float sum = 0.f;
    for (int t = g; t < T_TOK; t += 32) sum += g_probs[t * NE + e];
    sh[tid] = sum;
    __syncthreads();
#pragma unroll
    for (int st = 128; st >= 8; st >>= 1) {
        if (tid < st) sh[tid] += sh[tid + st];
        __syncthreads();
    }
    if (tid == 0) {
        int o = 0;
        g_off[0] = 0;
#pragma unroll
        for (int i = 0; i < NE; i++) {
            o += ((g_counts[i] + BM - 1) / BM) * BM;
            g_off[i + 1] = o;
        }
        float aux = 0.f;
#pragma unroll
        for (int i = 0; i < NE; i++) aux += (float)g_counts[i] * sh[i];
        aux *= (float)NE / ((float)T_TOK * (float)T_TOK);
        if (aux_out) *aux_out = aux;
    }
}

// ---------------- kernel 3: fill pad markers ----------------
__global__ void fill_kernel() {
    int i = blockIdx.x * blockDim.x + threadIdx.x;
    if (i < ROWS_CAP) g_pair_tok[i] = -1;
}

// ---------------- kernel 4: build pair list ----------------
__global__ void build_kernel() {
    int t = blockIdx.x * blockDim.x + threadIdx.x;
    if (t >= T_TOK) return;
#pragma unroll
    for (int k = 0; k < TK; k++) {
        int e = g_topk_e[t * TK + k];
        int pos = g_off[e] + atomicAdd(&g_cursor[e], 1);
        g_pair_tok[pos] = t;
        g_slot[t * TK + k] = pos;
    }
}

// ---------------- kernel 5: split-bf16 A (per token: [hi | lo]) ----------------
__global__ __launch_bounds__(128) void convx_kernel(const float* __restrict__ x)
{
    int t = blockIdx.x;
    int i = threadIdx.x;
    const float4* xr = (const float4*)(x + (size_t)t * DHID + i * 8);
    float4 a = xr[0], c = xr[1];
    float v[8] = {a.x, a.y, a.z, a.w, c.x, c.y, c.z, c.w};
    uint32_t wh[4], wl[4];
#pragma unroll
    for (int j = 0; j < 4; j++) {
        __nv_bfloat16 h0 = __float2bfloat16(v[2 * j]);
        __nv_bfloat16 h1 = __float2bfloat16(v[2 * j + 1]);
        __nv_bfloat16 l0 = __float2bfloat16(v[2 * j] - __bfloat162float(h0));
        __nv_bfloat16 l1 = __float2bfloat16(v[2 * j + 1] - __bfloat162float(h1));
        wh[j] = ((uint32_t)__bfloat16_as_ushort(h1) << 16) | __bfloat16_as_ushort(h0);
        wl[j] = ((uint32_t)__bfloat16_as_ushort(l1) << 16) | __bfloat16_as_ushort(l0);
    }
    __nv_bfloat16* dst = g_A2 + (size_t)t * 2048 + i * 8;
    *(uint4*)dst          = make_uint4(wh[0], wh[1], wh[2], wh[3]);
    *(uint4*)(dst + 1024) = make_uint4(wl[0], wl[1], wl[2], wl[3]);
}

// ---------------- kernel 6: split-bf16 B (per expert [Wh|Wl], k-major rows of n) ----------------
__global__ __launch_bounds__(256) void convw_kernel(const float* __restrict__ W)
{
    int i = blockIdx.x * 256 + threadIdx.x;   // float4 units: NE*DHID*DHID/4 = 2M
    float4 v = ((const float4*)W)[i];
    int n4 = i & 255;
    int k  = (i >> 8) & 1023;
    int e  = i >> 18;
    float vv[4] = {v.x, v.y, v.z, v.w};
    uint32_t wh[2], wl[2];
#pragma unroll
    for (int j = 0; j < 2; j++) {
        __nv_bfloat16 h0 = __float2bfloat16(vv[2 * j]);
        __nv_bfloat16 h1 = __float2bfloat16(vv[2 * j + 1]);
        __nv_bfloat16 l0 = __float2bfloat16(vv[2 * j] - __bfloat162float(h0));
        __nv_bfloat16 l1 = __float2bfloat16(vv[2 * j + 1] - __bfloat162float(h1));
        wh[j] = ((uint32_t)__bfloat16_as_ushort(h1) << 16) | __bfloat16_as_ushort(h0);
        wl[j] = ((uint32_t)__bfloat16_as_ushort(l1) << 16) | __bfloat16_as_ushort(l0);
    }
    size_t base = ((size_t)e * 2048 + k) * DHID + n4 * 4;
    *(uint2*)(g_B2 + base)                         = make_uint2(wh[0], wh[1]);
    *(uint2*)(g_B2 + base + (size_t)KHALF * DHID)  = make_uint2(wl[0], wl[1]);
}

// ---------------- kernel 7: grouped bf16 mma.sync GEMM (3-pass split) ----------------
// Y[row, n] = xh*Wh + xh*Wl + xl*Wh
__global__ __launch_bounds__(256) void gemm_kernel()
{
    extern __shared__ char dsm[];
    const int off8 = g_off[NE];
    const int m0 = blockIdx.y * BM;
    if (m0 >= off8) return;
    const int n0 = blockIdx.x * BN;
    const int tid = threadIdx.x;
    const int lane = tid & 31, wid = tid >> 5;

    int e = 0;
#pragma unroll
    for (int i = 1; i < NE; i++) if (m0 >= g_off[i]) e = i;
    const __nv_bfloat16* __restrict__ B2e = g_B2 + (size_t)e * 2048 * DHID;

    const uint32_t sb = smem_u32(dsm);

    // A loader: tid[7] selects hi/lo tile, tid[6:0] = row
    const int arow  = tid & 127;
    const int atile = tid >> 7;
    const int tok = g_pair_tok[m0 + arow];
    const __nv_bfloat16* asrc0 = g_A2 + (size_t)(tok < 0 ? 0 : tok) * 2048 + atile * KHALF;
    const int asz = (tok < 0) ? 0 : 16;
    const uint32_t adst = (atile ? AL_OFF : AH_OFF) + arow * 144;

    // B loader: tid[7] tile, tid[6:1] k-row, tid[0] half-row (128B)
    const int btile = tid >> 7;
    const int brow  = (tid >> 1) & 63;
    const int bhalf = tid & 1;
    const uint32_t bdst = (btile ? BL_OFF : BH_OFF) + brow * 272 + bhalf * 128;

    auto load_stage = [&](int st, int kt) {
        uint32_t stg = sb + st * STAGE_BYTES;
        int kb = kt * BKB;
        const char* as = (const char*)(asrc0 + kb);
        uint32_t ad = stg + adst;
#pragma unroll
        for (int c = 0; c < 8; c++) cp16z(ad + c * 16, as + c * 16, asz);
        const char* bs = (const char*)(B2e + ((size_t)(btile * KHALF + kb + brow)) * DHID + n0 + bhalf * 64);
        uint32_t bd = stg + bdst;
#pragma unroll
        for (int c = 0; c < 8; c++) cp16(bd + c * 16, bs + c * 16);
    };

    const int wm = (wid & 1) * 64;
    const int wn = (wid >> 1) * 32;

    float acc[4][4][4];
#pragma unroll
    for (int a = 0; a < 4; a++)
#pragma unroll
        for (int b = 0; b < 4; b++)
#pragma unroll
            for (int c = 0; c < 4; c++) acc[a][b][c] = 0.f;

    load_stage(0, 0); CP_COMMIT();
    load_stage(1, 1); CP_COMMIT();

    for (int kt = 0; kt < NK; kt++) {
        if (kt + 2 < NK) load_stage((kt + 2) % NST, kt + 2);
        CP_COMMIT();
        CP_WAIT(2);
        __syncthreads();

        uint32_t stg = sb + (kt % NST) * STAGE_BYTES;
#pragma unroll
        for (int p = 0; p < 3; p++) {
            uint32_t aB = stg + (p == 2 ? AL_OFF : AH_OFF) + wm * 144;
            uint32_t bB = stg + (p == 1 ? BL_OFF : BH_OFF);
#pragma unroll
            for (int kk = 0; kk < 4; kk++) {
                uint32_t a[4][4], bf[2][4];
#pragma unroll
                for (int mi = 0; mi < 4; mi++)
                    ldsm4(a[mi], aB + (mi * 16 + (lane & 15)) * 144 + kk * 32 + ((lane >> 4) << 4));
#pragma unroll
                for (int nh = 0; nh < 2; nh++)
                    ldsm4t(bf[nh], bB + (kk * 16 + (lane & 15)) * 272 + (wn + nh * 16 + ((lane >> 4) << 3)) * 2);
#pragma unroll
                for (int mi = 0; mi < 4; mi++)
#pragma unroll
                    for (int nj = 0; nj < 4; nj++)
                        mma16816(acc[mi][nj], a[mi], &bf[nj >> 1][(nj & 1) * 2]);
            }
        }
        __syncthreads();
    }

    // epilogue: registers -> g_Y
#pragma unroll
    for (int mi = 0; mi < 4; mi++) {
        int r0 = m0 + wm + mi * 16 + (lane >> 2);
#pragma unroll
        for (int nj = 0; nj < 4; nj++) {
            int c0 = n0 + wn + nj * 8 + (lane & 3) * 2;
            *(float2*)(g_Y + (size_t)r0 * DHID + c0)       = make_float2(acc[mi][nj][0], acc[mi][nj][1]);
            *(float2*)(g_Y + (size_t)(r0 + 8) * DHID + c0) = make_float2(acc[mi][nj][2], acc[mi][nj][3]);
        }
    }
}

// ---------------- kernel 8: weighted combine ----------------
__global__ __launch_bounds__(256) void combine_kernel(
    const float* __restrict__ b, float* __restrict__ out)
{
    int idx = blockIdx.x * blockDim.x + threadIdx.x;
    int t = idx >> 8;
    int f = (idx & 255) << 2;
    float4 r = make_float4(0.f, 0.f, 0.f, 0.f);
#pragma unroll
    for (int k = 0; k < TK; k++) {
        int e   = g_topk_e[t * TK + k];
        float w = g_topk_w[t * TK + k];
        int sl  = g_slot[t * TK + k];
        float4 yv = *(const float4*)(g_Y + (size_t)sl * DHID + f);
        float4 bv = *(const float4*)(b + (size_t)e * DHID + f);
        r.x = fmaf(w, yv.x + bv.x, r.x);
        r.y = fmaf(w, yv.y + bv.y, r.y);
        r.z = fmaf(w, yv.z + bv.z, r.z);
        r.w = fmaf(w, yv.w + bv.w, r.w);
    }
    *(float4*)(out + (size_t)t * DHID + f) = r;
}

// ---------------- launch ----------------
extern "C" void kernel_launch(void* const* d_in, const int* in_sizes, int n_in,
                              void* d_out, int out_size)
{
    const float* x  = (const float*)d_in[0];
    const float* Wg = (const float*)d_in[1];
    const float* bg = (const float*)d_in[2];
    const float* W  = (const float*)d_in[3];
    const float* b  = (const float*)d_in[4];
    float* out = (float*)d_out;

    float* aux_out = (out_size > T_TOK * DHID) ? out + (size_t)T_TOK * DHID : nullptr;

    cudaFuncSetAttribute(gemm_kernel, cudaFuncAttributeMaxDynamicSharedMemorySize, SMEM_DYN);

    init_kernel<<<1, 32>>>();
    convw_kernel<<<NE * DHID * DHID / 4 / 256, 256>>>(W);
    convx_kernel<<<T_TOK, 128>>>(x);
    router_kernel<<<T_TOK, 128>>>(x, Wg, bg);
    finalize_kernel<<<1, 256>>>(aux_out);
    fill_kernel<<<(ROWS_CAP + 255) / 256, 256>>>();
    build_kernel<<<(T_TOK + 255) / 256, 256>>>();
    gemm_kernel<<<dim3(DHID / BN, MTILES), 256, SMEM_DYN>>>();
    combine_kernel<<<(T_TOK * DHID / 4 + 255) / 256, 256>>>(b, out);
}

// round 5
// speedup vs baseline: 4.8309x; 2.9924x over previous
#include <cuda_runtime.h>
#include <cuda_fp16.h>
#include <cstdint>
#include <cstddef>

// Problem constants
#define T_TOK 8192
#define DHID  1024
#define NE    8
#define TK    4

// GEMM config (fp16 single pass)
#define BM    128
#define BN    128
#define BKB   64                  // k per stage
#define NST   3
#define NK    (DHID / BKB)        // 16
#define MTILES 264
#define ROWS_CAP (MTILES * BM)    // 33792

// smem stage: A 128x64 fp16 (16KB, 128B rows, XOR swizzle) + B 64x128 fp16 (16KB, 256B rows)
#define A_OFF 0
#define B_OFF 16384
#define STAGE_BYTES 32768
#define SMEM_DYN (NST * STAGE_BYTES)   // 98304

// ---------------- scratch (device globals; no allocation) ----------------
__device__ __half g_Ah[(size_t)T_TOK * DHID];            // fp16(x)
__device__ __half g_Bh[(size_t)NE * DHID * DHID];        // fp16(W), [e][k][n]
__device__ float g_Y[(size_t)ROWS_CAP * DHID];
__device__ int   g_pair_tok[ROWS_CAP];
__device__ int   g_slot[T_TOK * TK];
__device__ int   g_topk_e[T_TOK * TK];
__device__ float g_topk_w[T_TOK * TK];
__device__ float g_probs[T_TOK * NE];
__device__ int   g_counts[NE];
__device__ int   g_cursor[NE];
__device__ int   g_off[NE + 1];

// ---------------- PTX helpers (sm_80-compatible) ----------------
__device__ __forceinline__ uint32_t h2_as_u32(__half2 h) {
    uint32_t u;
    *(__half2*)&u = h;
    return u;
}
__device__ __forceinline__ uint32_t smem_u32(const void* p) {
    uint32_t a;
    asm("{ .reg .u64 t; cvta.to.shared.u64 t, %1; cvt.u32.u64 %0, t; }" : "=r"(a) : "l"(p));
    return a;
}
__device__ __forceinline__ void cp16(uint32_t dst, const void* src) {
    asm volatile("cp.async.cg.shared.global [%0], [%1], 16;" :: "r"(dst), "l"(src));
}
__device__ __forceinline__ void cp16z(uint32_t dst, const void* src, int sz) {
    asm volatile("cp.async.cg.shared.global [%0], [%1], 16, %2;" :: "r"(dst), "l"(src), "r"(sz));
}
#define CP_COMMIT() asm volatile("cp.async.commit_group;" ::: "memory")
#define CP_WAIT(n)  asm volatile("cp.async.wait_group %0;" :: "n"(n) : "memory")

__device__ __forceinline__ void ldsm4(uint32_t* r, uint32_t addr) {
    asm volatile("ldmatrix.sync.aligned.m8n8.x4.shared.b16 {%0,%1,%2,%3}, [%4];"
        : "=r"(r[0]), "=r"(r[1]), "=r"(r[2]), "=r"(r[3]) : "r"(addr));
}
__device__ __forceinline__ void ldsm4t(uint32_t* r, uint32_t addr) {
    asm volatile("ldmatrix.sync.aligned.m8n8.x4.trans.shared.b16 {%0,%1,%2,%3}, [%4];"
        : "=r"(r[0]), "=r"(r[1]), "=r"(r[2]), "=r"(r[3]) : "r"(addr));
}
__device__ __forceinline__ void mma16816(float* c, const uint32_t* a, const uint32_t* b) {
    asm volatile("mma.sync.aligned.m16n8k16.row.col.f32.f16.f16.f32 "
        "{%0,%1,%2,%3}, {%4,%5,%6,%7}, {%8,%9}, {%0,%1,%2,%3};"
        : "+f"(c[0]), "+f"(c[1]), "+f"(c[2]), "+f"(c[3])
        : "r"(a[0]), "r"(a[1]), "r"(a[2]), "r"(a[3]), "r"(b[0]), "r"(b[1]));
}

// ---------------- kernel 0: zero counters ----------------
__global__ void init_kernel() {
    int i = threadIdx.x;
    if (i < NE) { g_counts[i] = 0; g_cursor[i] = 0; }
}

// ---------------- kernel 1: router (vectorized Wg loads) ----------------
__global__ __launch_bounds__(128) void router_kernel(
    const float* __restrict__ x, const float* __restrict__ Wg,
    const float* __restrict__ bg)
{
    int t = blockIdx.x;
    const float* xr = x + (size_t)t * DHID;
    float acc[NE];
#pragma unroll
    for (int e = 0; e < NE; e++) acc[e] = 0.f;

    for (int d = threadIdx.x; d < DHID; d += 128) {
        float xv = xr[d];
        float4 w0 = *(const float4*)(Wg + d * NE);
        float4 w1 = *(const float4*)(Wg + d * NE + 4);
        acc[0] = fmaf(xv, w0.x, acc[0]); acc[1] = fmaf(xv, w0.y, acc[1]);
        acc[2] = fmaf(xv, w0.z, acc[2]); acc[3] = fmaf(xv, w0.w, acc[3]);
        acc[4] = fmaf(xv, w1.x, acc[4]); acc[5] = fmaf(xv, w1.y, acc[5]);
        acc[6] = fmaf(xv, w1.z, acc[6]); acc[7] = fmaf(xv, w1.w, acc[7]);
    }
#pragma unroll
    for (int off = 16; off > 0; off >>= 1)
#pragma unroll
        for (int e = 0; e < NE; e++)
            acc[e] += __shfl_down_sync(0xffffffffu, acc[e], off);

    __shared__ float s[4][NE];
    int warp = threadIdx.x >> 5, lane = threadIdx.x & 31;
    if (lane == 0)
#pragma unroll
        for (int e = 0; e < NE; e++) s[warp][e] = acc[e];
    __syncthreads();

    if (threadIdx.x == 0) {
        float logit[NE], p[NE];
        float mx = -1e30f;
#pragma unroll
        for (int e = 0; e < NE; e++) {
            logit[e] = s[0][e] + s[1][e] + s[2][e] + s[3][e] + bg[e];
            mx = fmaxf(mx, logit[e]);
        }
        float sum = 0.f;
#pragma unroll
        for (int e = 0; e < NE; e++) { p[e] = __expf(logit[e] - mx); sum += p[e]; }
        float inv = 1.0f / sum;
#pragma unroll
        for (int e = 0; e < NE; e++) { p[e] *= inv; g_probs[t * NE + e] = p[e]; }

        bool used[NE];
#pragma unroll
        for (int e = 0; e < NE; e++) used[e] = false;
        int   idxs[TK];
        float vals[TK];
        float psel = 0.f;
#pragma unroll
        for (int k = 0; k < TK; k++) {
            int best = -1; float bv = -1.f;
#pragma unroll
            for (int e = 0; e < NE; e++)
                if (!used[e] && p[e] > bv) { bv = p[e]; best = e; }
            used[best] = true;
            idxs[k] = best; vals[k] = bv; psel += bv;
        }
        float winv = 1.0f / (psel + 1e-6f);
#pragma unroll
        for (int k = 0; k < TK; k++) {
            g_topk_e[t * TK + k] = idxs[k];
            g_topk_w[t * TK + k] = vals[k] * winv;
            atomicAdd(&g_counts[idxs[k]], 1);
        }
    }
}

// ---------------- kernel 2: deterministic probs reduce + scan + aux ----------------
__global__ __launch_bounds__(256) void finalize_kernel(float* aux_out)
{
    __shared__ float sh[256];
    int tid = threadIdx.x;
    int e = tid & 7, g = tid >> 3;
    float sum = 0.f;
    for (int t = g; t < T_TOK; t += 32) sum += g_probs[t * NE + e];
    sh[tid] = sum;
    __syncthreads();
#pragma unroll
    for (int st = 128; st >= 8; st >>= 1) {
        if (tid < st) sh[tid] += sh[tid + st];
        __syncthreads();
    }
    if (tid == 0) {
        int o = 0;
        g_off[0] = 0;
#pragma unroll
        for (int i = 0; i < NE; i++) {
            o += ((g_counts[i] + BM - 1) / BM) * BM;
            g_off[i + 1] = o;
        }
        float aux = 0.f;
#pragma unroll
        for (int i = 0; i < NE; i++) aux += (float)g_counts[i] * sh[i];
        aux *= (float)NE / ((float)T_TOK * (float)T_TOK);
        if (aux_out) *aux_out = aux;
    }
}

// ---------------- kernel 3: fill pad markers ----------------
__global__ void fill_kernel() {
    int i = blockIdx.x * blockDim.x + threadIdx.x;
    if (i < ROWS_CAP) g_pair_tok[i] = -1;
}

// ---------------- kernel 4: build pair list ----------------
__global__ void build_kernel() {
    int t = blockIdx.x * blockDim.x + threadIdx.x;
    if (t >= T_TOK) return;
#pragma unroll
    for (int k = 0; k < TK; k++) {
        int e = g_topk_e[t * TK + k];
        int pos = g_off[e] + atomicAdd(&g_cursor[e], 1);
        g_pair_tok[pos] = t;
        g_slot[t * TK + k] = pos;
    }
}

// ---------------- kernel 5: x -> fp16 ----------------
__global__ __launch_bounds__(256) void convx_kernel(const float* __restrict__ x)
{
    int i = blockIdx.x * 256 + threadIdx.x;   // over T*D/8
    const float4* src = (const float4*)x + (size_t)i * 2;
    float4 a = src[0], c = src[1];
    __half2 h0 = __float22half2_rn(make_float2(a.x, a.y));
    __half2 h1 = __float22half2_rn(make_float2(a.z, a.w));
    __half2 h2 = __float22half2_rn(make_float2(c.x, c.y));
    __half2 h3 = __float22half2_rn(make_float2(c.z, c.w));
    *(uint4*)(g_Ah + (size_t)i * 8) = make_uint4(
        h2_as_u32(h0), h2_as_u32(h1), h2_as_u32(h2), h2_as_u32(h3));
}

// ---------------- kernel 6: W -> fp16 ----------------
__global__ __launch_bounds__(256) void convw_kernel(const float* __restrict__ W)
{
    size_t i = (size_t)blockIdx.x * 256 + threadIdx.x;   // over NE*D*D/8
    const float4* src = (const float4*)W + i * 2;
    float4 a = src[0], c = src[1];
    __half2 h0 = __float22half2_rn(make_float2(a.x, a.y));
    __half2 h1 = __float22half2_rn(make_float2(a.z, a.w));
    __half2 h2 = __float22half2_rn(make_float2(c.x, c.y));
    __half2 h3 = __float22half2_rn(make_float2(c.z, c.w));
    *(uint4*)(g_Bh + i * 8) = make_uint4(
        h2_as_u32(h0), h2_as_u32(h1), h2_as_u32(h2), h2_as_u32(h3));
}

// ---------------- kernel 7: grouped fp16 mma.sync GEMM ----------------
__global__ __launch_bounds__(256, 2) void gemm_kernel()
{
    extern __shared__ char dsm[];
    const int off8 = g_off[NE];
    const int m0 = blockIdx.y * BM;
    if (m0 >= off8) return;
    const int n0 = blockIdx.x * BN;
    const int tid = threadIdx.x;
    const int lane = tid & 31, wid = tid >> 5;

    int e = 0;
#pragma unroll
    for (int i = 1; i < NE; i++) if (m0 >= g_off[i]) e = i;
    const __half* __restrict__ Be = g_Bh + (size_t)e * DHID * DHID;

    const uint32_t sb = smem_u32(dsm);

    // A loader: thread t -> row t>>1, chunks (t&1)*4..+3 (16B chunks of 128B row)
    const int arow = tid >> 1;
    const int ac0  = (tid & 1) * 4;
    const int tok = g_pair_tok[m0 + arow];
    const __half* asrc0 = g_Ah + (size_t)(tok < 0 ? 0 : tok) * DHID;
    const int asz = (tok < 0) ? 0 : 16;
    // B loader: thread t -> krow t>>2, chunks (t&3)*4..+3 (16B chunks of 256B row)
    const int brow = tid >> 2;
    const int bc0  = (tid & 3) * 4;

    auto load_stage = [&](int st, int kt) {
        uint32_t stg = sb + st * STAGE_BYTES;
        int kb = kt * BKB;
        const char* as = (const char*)(asrc0 + kb + ac0 * 8);
        uint32_t ad = stg + A_OFF + arow * 128;
        int ar7 = arow & 7;
#pragma unroll
        for (int c = 0; c < 4; c++)
            cp16z(ad + (((ac0 + c) ^ ar7) << 4), as + c * 16, asz);
        const char* bs = (const char*)(Be + (size_t)(kb + brow) * DHID + n0 + bc0 * 8);
        uint32_t bd = stg + B_OFF + brow * 256;
        int br7 = brow & 7;
#pragma unroll
        for (int c = 0; c < 4; c++)
            cp16(bd + (((bc0 + c) ^ br7) << 4), bs + c * 16);
    };

    const int wm = (wid & 1) * 64;           // warp m-offset
    const int wn = (wid >> 1) * 32;          // warp n-offset

    float acc[4][4][4];
#pragma unroll
    for (int a = 0; a < 4; a++)
#pragma unroll
        for (int b = 0; b < 4; b++)
#pragma unroll
            for (int c = 0; c < 4; c++) acc[a][b][c] = 0.f;

    load_stage(0, 0); CP_COMMIT();
    load_stage(1, 1); CP_COMMIT();

    const int l15 = lane & 15;
    const int l4  = lane >> 4;

    for (int kt = 0; kt < NK; kt++) {
        if (kt + 2 < NK) load_stage((kt + 2) % NST, kt + 2);
        CP_COMMIT();
        CP_WAIT(2);
        __syncthreads();

        uint32_t stg = sb + (kt % NST) * STAGE_BYTES;
        uint32_t aB = stg + A_OFF;
        uint32_t bB = stg + B_OFF;
#pragma unroll
        for (int kk = 0; kk < 4; kk++) {
            uint32_t a[4][4], bf[2][4];
#pragma unroll
            for (int mi = 0; mi < 4; mi++) {
                int row = wm + mi * 16 + l15;
                int c = kk * 2 + l4;
                ldsm4(a[mi], aB + row * 128 + ((c ^ (row & 7)) << 4));
            }
#pragma unroll
            for (int nh = 0; nh < 2; nh++) {
                int row = kk * 16 + l15;
                int c = (wn >> 3) + nh * 2 + l4;
                ldsm4t(bf[nh], bB + row * 256 + ((c ^ (row & 7)) << 4));
            }
#pragma unroll
            for (int mi = 0; mi < 4; mi++)
#pragma unroll
                for (int nj = 0; nj < 4; nj++)
                    mma16816(acc[mi][nj], a[mi], &bf[nj >> 1][(nj & 1) * 2]);
        }
        __syncthreads();
    }

    // epilogue: registers -> g_Y
#pragma unroll
    for (int mi = 0; mi < 4; mi++) {
        int r0 = m0 + wm + mi * 16 + (lane >> 2);
#pragma unroll
        for (int nj = 0; nj < 4; nj++) {
            int c0 = n0 + wn + nj * 8 + (lane & 3) * 2;
            *(float2*)(g_Y + (size_t)r0 * DHID + c0)       = make_float2(acc[mi][nj][0], acc[mi][nj][1]);
            *(float2*)(g_Y + (size_t)(r0 + 8) * DHID + c0) = make_float2(acc[mi][nj][2], acc[mi][nj][3]);
        }
    }
}

// ---------------- kernel 8: weighted combine ----------------
__global__ __launch_bounds__(256) void combine_kernel(
    const float* __restrict__ b, float* __restrict__ out)
{
    int idx = blockIdx.x * blockDim.x + threadIdx.x;
    int t = idx >> 8;
    int f = (idx & 255) << 2;
    float4 r = make_float4(0.f, 0.f, 0.f, 0.f);
#pragma unroll
    for (int k = 0; k < TK; k++) {
        int e   = g_topk_e[t * TK + k];
        float w = g_topk_w[t * TK + k];
        int sl  = g_slot[t * TK + k];
        float4 yv = *(const float4*)(g_Y + (size_t)sl * DHID + f);
        float4 bv = *(const float4*)(b + (size_t)e * DHID + f);
        r.x = fmaf(w, yv.x + bv.x, r.x);
        r.y = fmaf(w, yv.y + bv.y, r.y);
        r.z = fmaf(w, yv.z + bv.z, r.z);
        r.w = fmaf(w, yv.w + bv.w, r.w);
    }
    *(float4*)(out + (size_t)t * DHID + f) = r;
}

// ---------------- launch ----------------
extern "C" void kernel_launch(void* const* d_in, const int* in_sizes, int n_in,
                              void* d_out, int out_size)
{
    const float* x  = (const float*)d_in[0];
    const float* Wg = (const float*)d_in[1];
    const float* bg = (const float*)d_in[2];
    const float* W  = (const float*)d_in[3];
    const float* b  = (const float*)d_in[4];
    float* out = (float*)d_out;

    float* aux_out = (out_size > T_TOK * DHID) ? out + (size_t)T_TOK * DHID : nullptr;

    cudaFuncSetAttribute(gemm_kernel, cudaFuncAttributeMaxDynamicSharedMemorySize, SMEM_DYN);

    init_kernel<<<1, 32>>>();
    convw_kernel<<<NE * DHID * DHID / 8 / 256, 256>>>(W);
    convx_kernel<<<T_TOK * DHID / 8 / 256, 256>>>(x);
    router_kernel<<<T_TOK, 128>>>(x, Wg, bg);
    finalize_kernel<<<1, 256>>>(aux_out);
    fill_kernel<<<(ROWS_CAP + 255) / 256, 256>>>();
    build_kernel<<<(T_TOK + 255) / 256, 256>>>();
    gemm_kernel<<<dim3(DHID / BN, MTILES), 256, SMEM_DYN>>>();
    combine_kernel<<<(T_TOK * DHID / 4 + 255) / 256, 256>>>(b, out);
}

// round 6
// speedup vs baseline: 5.0513x; 1.0456x over previous
#include <cuda_runtime.h>
#include <cuda_fp16.h>
#include <cstdint>
#include <cstddef>

// Problem constants
#define T_TOK 8192
#define DHID  1024
#define NE    8
#define TK    4

// GEMM config (fp16 single pass)
#define BM    128
#define BN    128
#define BKB   64                  // k per stage
#define NST   3
#define NK    (DHID / BKB)        // 16
#define MTILES 264
#define ROWS_CAP (MTILES * BM)    // 33792

// smem stage: A 128x64 fp16 (16KB, 128B rows, XOR swizzle) + B 64x128 fp16 (16KB, 256B rows)
#define A_OFF 0
#define B_OFF 16384
#define STAGE_BYTES 32768
#define SMEM_DYN (NST * STAGE_BYTES)   // 98304

// ---------------- scratch (device globals; no allocation) ----------------
__device__ __half g_Ah[(size_t)T_TOK * DHID];            // fp16(x)
__device__ __half g_Bh[(size_t)NE * DHID * DHID];        // fp16(W), [e][k][n]
__device__ __half g_Yh[(size_t)ROWS_CAP * DHID];         // fp16 GEMM results
__device__ float g_WgT[NE * DHID];                       // Wg transposed [e][d]
__device__ int   g_pair_tok[ROWS_CAP];
__device__ int   g_slot[T_TOK * TK];
__device__ int   g_topk_e[T_TOK * TK];
__device__ float g_topk_w[T_TOK * TK];
__device__ float g_probs[T_TOK * NE];
__device__ int   g_counts[NE];
__device__ int   g_cursor[NE];
__device__ int   g_off[NE + 1];

// ---------------- PTX helpers (sm_80-compatible) ----------------
__device__ __forceinline__ uint32_t h2_as_u32(__half2 h) {
    uint32_t u;
    *(__half2*)&u = h;
    return u;
}
__device__ __forceinline__ uint32_t smem_u32(const void* p) {
    uint32_t a;
    asm("{ .reg .u64 t; cvta.to.shared.u64 t, %1; cvt.u32.u64 %0, t; }" : "=r"(a) : "l"(p));
    return a;
}
__device__ __forceinline__ void cp16(uint32_t dst, const void* src) {
    asm volatile("cp.async.cg.shared.global [%0], [%1], 16;" :: "r"(dst), "l"(src));
}
__device__ __forceinline__ void cp16z(uint32_t dst, const void* src, int sz) {
    asm volatile("cp.async.cg.shared.global [%0], [%1], 16, %2;" :: "r"(dst), "l"(src), "r"(sz));
}
#define CP_COMMIT() asm volatile("cp.async.commit_group;" ::: "memory")
#define CP_WAIT(n)  asm volatile("cp.async.wait_group %0;" :: "n"(n) : "memory")

__device__ __forceinline__ void ldsm4(uint32_t* r, uint32_t addr) {
    asm volatile("ldmatrix.sync.aligned.m8n8.x4.shared.b16 {%0,%1,%2,%3}, [%4];"
        : "=r"(r[0]), "=r"(r[1]), "=r"(r[2]), "=r"(r[3]) : "r"(addr));
}
__device__ __forceinline__ void ldsm4t(uint32_t* r, uint32_t addr) {
    asm volatile("ldmatrix.sync.aligned.m8n8.x4.trans.shared.b16 {%0,%1,%2,%3}, [%4];"
        : "=r"(r[0]), "=r"(r[1]), "=r"(r[2]), "=r"(r[3]) : "r"(addr));
}
__device__ __forceinline__ void mma16816(float* c, const uint32_t* a, const uint32_t* b) {
    asm volatile("mma.sync.aligned.m16n8k16.row.col.f32.f16.f16.f32 "
        "{%0,%1,%2,%3}, {%4,%5,%6,%7}, {%8,%9}, {%0,%1,%2,%3};"
        : "+f"(c[0]), "+f"(c[1]), "+f"(c[2]), "+f"(c[3])
        : "r"(a[0]), "r"(a[1]), "r"(a[2]), "r"(a[3]), "r"(b[0]), "r"(b[1]));
}

// ---------------- kernel 0: counters + pad fill + WgT transpose ----------------
__global__ __launch_bounds__(256) void initfill_kernel(const float* __restrict__ Wg)
{
    int i = blockIdx.x * 256 + threadIdx.x;
    if (i < NE) { g_counts[i] = 0; g_cursor[i] = 0; }
    if (i < ROWS_CAP) g_pair_tok[i] = -1;
    if (i < NE * DHID) {
        // Wg[d][e] (i = d*8+e) -> WgT[e][d]
        g_WgT[(i & 7) * DHID + (i >> 3)] = Wg[i];
    }
}

// ---------------- kernel 1: W -> fp16 and x -> fp16 (merged) ----------------
#define NW_CHUNKS ((size_t)NE * DHID * DHID / 8)   // 1048576
#define NX_CHUNKS ((size_t)T_TOK * DHID / 8)       // 1048576
__global__ __launch_bounds__(256) void conv_kernel(
    const float* __restrict__ W, const float* __restrict__ x)
{
    size_t i = (size_t)blockIdx.x * 256 + threadIdx.x;
    const float* src;
    __half* dst;
    if (i < NW_CHUNKS) { src = W + i * 8; dst = g_Bh + i * 8; }
    else { size_t j = i - NW_CHUNKS; src = x + j * 8; dst = g_Ah + j * 8; }
    float4 a = ((const float4*)src)[0], c = ((const float4*)src)[1];
    __half2 h0 = __float22half2_rn(make_float2(a.x, a.y));
    __half2 h1 = __float22half2_rn(make_float2(a.z, a.w));
    __half2 h2 = __float22half2_rn(make_float2(c.x, c.y));
    __half2 h3 = __float22half2_rn(make_float2(c.z, c.w));
    *(uint4*)dst = make_uint4(h2_as_u32(h0), h2_as_u32(h1), h2_as_u32(h2), h2_as_u32(h3));
}

// ---------------- kernel 2: router (smem WgT, warp-per-token) ----------------
__global__ __launch_bounds__(256) void router_kernel(
    const float* __restrict__ x, const float* __restrict__ bg)
{
    __shared__ float wgs[NE * DHID];   // 32KB: wgs[e*1024 + d]
    for (int i = threadIdx.x; i < NE * DHID; i += 256)
        wgs[i] = g_WgT[i];
    __syncthreads();

    int warp = threadIdx.x >> 5, lane = threadIdx.x & 31;

    for (int tt = 0; tt < 4; tt++) {
        int t = blockIdx.x * 32 + tt * 8 + warp;
        const float* xr = x + (size_t)t * DHID;

        float xv[32];
#pragma unroll
        for (int i = 0; i < 32; i++) xv[i] = xr[lane + 32 * i];

        float acc[NE];
#pragma unroll
        for (int e = 0; e < NE; e++) acc[e] = 0.f;
#pragma unroll
        for (int e = 0; e < NE; e++) {
            const float* wr = wgs + e * DHID + lane;
#pragma unroll
            for (int i = 0; i < 32; i++)
                acc[e] = fmaf(xv[i], wr[32 * i], acc[e]);
        }
#pragma unroll
        for (int off = 16; off > 0; off >>= 1)
#pragma unroll
            for (int e = 0; e < NE; e++)
                acc[e] += __shfl_down_sync(0xffffffffu, acc[e], off);

        if (lane == 0) {
            float logit[NE], p[NE];
            float mx = -1e30f;
#pragma unroll
            for (int e = 0; e < NE; e++) {
                logit[e] = acc[e] + bg[e];
                mx = fmaxf(mx, logit[e]);
            }
            float sum = 0.f;
#pragma unroll
            for (int e = 0; e < NE; e++) { p[e] = __expf(logit[e] - mx); sum += p[e]; }
            float inv = 1.0f / sum;
#pragma unroll
            for (int e = 0; e < NE; e++) { p[e] *= inv; g_probs[t * NE + e] = p[e]; }

            bool used[NE];
#pragma unroll
            for (int e = 0; e < NE; e++) used[e] = false;
            int   idxs[TK];
            float vals[TK];
            float psel = 0.f;
#pragma unroll
            for (int k = 0; k < TK; k++) {
                int best = -1; float bv = -1.f;
#pragma unroll
                for (int e = 0; e < NE; e++)
                    if (!used[e] && p[e] > bv) { bv = p[e]; best = e; }
                used[best] = true;
                idxs[k] = best; vals[k] = bv; psel += bv;
            }
            float winv = 1.0f / (psel + 1e-6f);
#pragma unroll
            for (int k = 0; k < TK; k++) {
                g_topk_e[t * TK + k] = idxs[k];
                g_topk_w[t * TK + k] = vals[k] * winv;
                atomicAdd(&g_counts[idxs[k]], 1);
            }
        }
    }
}

// ---------------- kernel 3: deterministic probs reduce + scan + aux ----------------
__global__ __launch_bounds__(256) void finalize_kernel(float* aux_out)
{
    __shared__ float sh[256];
    int tid = threadIdx.x;
    int e = tid & 7, g = tid >> 3;
    float sum = 0.f;
    for (int t = g; t < T_TOK; t += 32) sum += g_probs[t * NE + e];
    sh[tid] = sum;
    __syncthreads();
#pragma unroll
    for (int st = 128; st >= 8; st >>= 1) {
        if (tid < st) sh[tid] += sh[tid + st];
        __syncthreads();
    }
    if (tid == 0) {
        int o = 0;
        g_off[0] = 0;
#pragma unroll
        for (int i = 0; i < NE; i++) {
            o += ((g_counts[i] + BM - 1) / BM) * BM;
            g_off[i + 1] = o;
        }
        float aux = 0.f;
#pragma unroll
        for (int i = 0; i < NE; i++) aux += (float)g_counts[i] * sh[i];
        aux *= (float)NE / ((float)T_TOK * (float)T_TOK);
        if (aux_out) *aux_out = aux;
    }
}

// ---------------- kernel 4: build pair list ----------------
__global__ void build_kernel() {
    int t = blockIdx.x * blockDim.x + threadIdx.x;
    if (t >= T_TOK) return;
#pragma unroll
    for (int k = 0; k < TK; k++) {
        int e = g_topk_e[t * TK + k];
        int pos = g_off[e] + atomicAdd(&g_cursor[e], 1);
        g_pair_tok[pos] = t;
        g_slot[t * TK + k] = pos;
    }
}

// ---------------- kernel 5: grouped fp16 mma.sync GEMM ----------------
__global__ __launch_bounds__(256, 2) void gemm_kernel()
{
    extern __shared__ char dsm[];
    const int off8 = g_off[NE];
    const int m0 = blockIdx.y * BM;
    if (m0 >= off8) return;
    const int n0 = blockIdx.x * BN;
    const int tid = threadIdx.x;
    const int lane = tid & 31, wid = tid >> 5;

    int e = 0;
#pragma unroll
    for (int i = 1; i < NE; i++) if (m0 >= g_off[i]) e = i;
    const __half* __restrict__ Be = g_Bh + (size_t)e * DHID * DHID;

    const uint32_t sb = smem_u32(dsm);

    // A loader: thread t -> row t>>1, chunks (t&1)*4..+3 (16B chunks of 128B row)
    const int arow = tid >> 1;
    const int ac0  = (tid & 1) * 4;
    const int tok = g_pair_tok[m0 + arow];
    const __half* asrc0 = g_Ah + (size_t)(tok < 0 ? 0 : tok) * DHID;
    const int asz = (tok < 0) ? 0 : 16;
    // B loader: thread t -> krow t>>2, chunks (t&3)*4..+3 (16B chunks of 256B row)
    const int brow = tid >> 2;
    const int bc0  = (tid & 3) * 4;

    auto load_stage = [&](int st, int kt) {
        uint32_t stg = sb + st * STAGE_BYTES;
        int kb = kt * BKB;
        const char* as = (const char*)(asrc0 + kb + ac0 * 8);
        uint32_t ad = stg + A_OFF + arow * 128;
        int ar7 = arow & 7;
#pragma unroll
        for (int c = 0; c < 4; c++)
            cp16z(ad + (((ac0 + c) ^ ar7) << 4), as + c * 16, asz);
        const char* bs = (const char*)(Be + (size_t)(kb + brow) * DHID + n0 + bc0 * 8);
        uint32_t bd = stg + B_OFF + brow * 256;
        int br7 = brow & 7;
#pragma unroll
        for (int c = 0; c < 4; c++)
            cp16(bd + (((bc0 + c) ^ br7) << 4), bs + c * 16);
    };

    const int wm = (wid & 1) * 64;           // warp m-offset
    const int wn = (wid >> 1) * 32;          // warp n-offset

    float acc[4][4][4];
#pragma unroll
    for (int a = 0; a < 4; a++)
#pragma unroll
        for (int b = 0; b < 4; b++)
#pragma unroll
            for (int c = 0; c < 4; c++) acc[a][b][c] = 0.f;

    load_stage(0, 0); CP_COMMIT();
    load_stage(1, 1); CP_COMMIT();

    const int l15 = lane & 15;
    const int l4  = lane >> 4;

    for (int kt = 0; kt < NK; kt++) {
        if (kt + 2 < NK) load_stage((kt + 2) % NST, kt + 2);
        CP_COMMIT();
        CP_WAIT(2);
        __syncthreads();

        uint32_t stg = sb + (kt % NST) * STAGE_BYTES;
        uint32_t aB = stg + A_OFF;
        uint32_t bB = stg + B_OFF;
#pragma unroll
        for (int kk = 0; kk < 4; kk++) {
            uint32_t a[4][4], bf[2][4];
#pragma unroll
            for (int mi = 0; mi < 4; mi++) {
                int row = wm + mi * 16 + l15;
                int c = kk * 2 + l4;
                ldsm4(a[mi], aB + row * 128 + ((c ^ (row & 7)) << 4));
            }
#pragma unroll
            for (int nh = 0; nh < 2; nh++) {
                int row = kk * 16 + l15;
                int c = (wn >> 3) + nh * 2 + l4;
                ldsm4t(bf[nh], bB + row * 256 + ((c ^ (row & 7)) << 4));
            }
#pragma unroll
            for (int mi = 0; mi < 4; mi++)
#pragma unroll
                for (int nj = 0; nj < 4; nj++)
                    mma16816(acc[mi][nj], a[mi], &bf[nj >> 1][(nj & 1) * 2]);
        }
        __syncthreads();
    }

    // epilogue: registers -> g_Yh (fp16)
#pragma unroll
    for (int mi = 0; mi < 4; mi++) {
        int r0 = m0 + wm + mi * 16 + (lane >> 2);
#pragma unroll
        for (int nj = 0; nj < 4; nj++) {
            int c0 = n0 + wn + nj * 8 + (lane & 3) * 2;
            __half2 lo = __float22half2_rn(make_float2(acc[mi][nj][0], acc[mi][nj][1]));
            __half2 hi = __float22half2_rn(make_float2(acc[mi][nj][2], acc[mi][nj][3]));
            *(__half2*)(g_Yh + (size_t)r0 * DHID + c0)       = lo;
            *(__half2*)(g_Yh + (size_t)(r0 + 8) * DHID + c0) = hi;
        }
    }
}

// ---------------- kernel 6: weighted combine (fp16 Y) ----------------
__global__ __launch_bounds__(256) void combine_kernel(
    const float* __restrict__ b, float* __restrict__ out)
{
    int idx = blockIdx.x * blockDim.x + threadIdx.x;
    int t = idx >> 8;
    int f = (idx & 255) << 2;
    float4 r = make_float4(0.f, 0.f, 0.f, 0.f);
#pragma unroll
    for (int k = 0; k < TK; k++) {
        int e   = g_topk_e[t * TK + k];
        float w = g_topk_w[t * TK + k];
        int sl  = g_slot[t * TK + k];
        uint2 yraw = *(const uint2*)(g_Yh + (size_t)sl * DHID + f);
        float2 y01 = __half22float2(*(__half2*)&yraw.x);
        float2 y23 = __half22float2(*(__half2*)&yraw.y);
        float4 bv = *(const float4*)(b + (size_t)e * DHID + f);
        r.x = fmaf(w, y01.x + bv.x, r.x);
        r.y = fmaf(w, y01.y + bv.y, r.y);
        r.z = fmaf(w, y23.x + bv.z, r.z);
        r.w = fmaf(w, y23.y + bv.w, r.w);
    }
    *(float4*)(out + (size_t)t * DHID + f) = r;
}

// ---------------- launch ----------------
extern "C" void kernel_launch(void* const* d_in, const int* in_sizes, int n_in,
                              void* d_out, int out_size)
{
    const float* x  = (const float*)d_in[0];
    const float* Wg = (const float*)d_in[1];
    const float* bg = (const float*)d_in[2];
    const float* W  = (const float*)d_in[3];
    const float* b  = (const float*)d_in[4];
    float* out = (float*)d_out;

    float* aux_out = (out_size > T_TOK * DHID) ? out + (size_t)T_TOK * DHID : nullptr;

    cudaFuncSetAttribute(gemm_kernel, cudaFuncAttributeMaxDynamicSharedMemorySize, SMEM_DYN);

    initfill_kernel<<<(ROWS_CAP + 255) / 256, 256>>>(Wg);                    // 0
    conv_kernel<<<(int)((NW_CHUNKS + NX_CHUNKS) / 256), 256>>>(W, x);        // 1
    router_kernel<<<T_TOK / 32, 256>>>(x, bg);                               // 2
    finalize_kernel<<<1, 256>>>(aux_out);                                    // 3
    build_kernel<<<(T_TOK + 255) / 256, 256>>>();                            // 4
    gemm_kernel<<<dim3(DHID / BN, MTILES), 256, SMEM_DYN>>>();               // 5  <- ncu captures this
    combine_kernel<<<(T_TOK * DHID / 4 + 255) / 256, 256>>>(b, out);         // 6
}